// round 3
// baseline (speedup 1.0000x reference)
#include <cuda_runtime.h>
#include <float.h>

#define C    64
#define K5   5
#define KKT  25
#define TAPS (C*KKT)      // 1600
#define BB   4
#define H    128
#define W    128
#define HW   (H*W)        // 16384
#define NPIX (BB*HW)      // 65536
#define NOUT (BB*C*HW)    // 4194304

// Scratch (static __device__ — no allocations allowed)
__device__ int   g_idx[C*TAPS];
__device__ float g_val[C*TAPS];
__device__ int   g_nnz[C];
__device__ float g_rowsum[C];
__device__ float g_s[NPIX];
__device__ float g_xmax[NPIX];
__device__ float g_m[BB*C];

__device__ __forceinline__ void atomicMaxF(float* addr, float v) {
    // works for mixed-sign floats with -FLT_MAX init
    if (v >= 0.0f) atomicMax((int*)addr, __float_as_int(v));
    else           atomicMin((unsigned int*)addr, __float_as_uint(v));
}

__global__ void k_init_m() {
    if (threadIdx.x < BB*C) g_m[threadIdx.x] = -FLT_MAX;
}

// Build per-out-channel sparse taps from W (64 x 1600). One warp per row.
__global__ void k_build(const float* __restrict__ wmat) {
    int warp = (blockIdx.x * blockDim.x + threadIdx.x) >> 5;
    int lane = threadIdx.x & 31;
    if (warp >= C) return;
    const float* row = wmat + warp * TAPS;
    int cnt = 0;
    float rsum = 0.0f;
    for (int base = 0; base < TAPS; base += 32) {
        float v = row[base + lane];
        rsum += v;
        unsigned mask = __ballot_sync(0xffffffffu, v != 0.0f);
        if (v != 0.0f) {
            int pos = __popc(mask & ((1u << lane) - 1u));
            int k = base + lane;
            int ci  = k / KKT;
            int rem = k - ci * KKT;
            int dj  = rem / K5;
            int dk  = rem - dj * K5;
            g_idx[warp * TAPS + cnt + pos] = (ci << 8) | (dj << 4) | dk;
            g_val[warp * TAPS + cnt + pos] = v;
        }
        cnt += __popc(mask);
    }
    #pragma unroll
    for (int off = 16; off; off >>= 1)
        rsum += __shfl_down_sync(0xffffffffu, rsum, off);
    if (lane == 0) { g_nnz[warp] = cnt; g_rowsum[warp] = rsum; }
}

// s[b,h,w] = sum over channels of x
__global__ void k_chansum(const float* __restrict__ x) {
    int p = blockIdx.x * blockDim.x + threadIdx.x;
    int b  = p >> 14;
    int hw = p & (HW - 1);
    const float* xb = x + (size_t)b * C * HW + hw;
    float s = 0.0f;
    #pragma unroll 8
    for (int i = 0; i < C; i++) s += xb[i * HW];
    g_s[p] = s;
}

// xmax[b,h,w] = max( 5x5 box-sum of s (zero pad), 5.0 )
__global__ void k_box() {
    int p  = blockIdx.x * blockDim.x + threadIdx.x;
    int b  = p >> 14;
    int hw = p & (HW - 1);
    int h  = hw >> 7;
    int w  = hw & 127;
    const float* sb = g_s + b * HW;
    float s = 0.0f;
    #pragma unroll
    for (int dj = -2; dj <= 2; dj++) {
        int hh = h + dj;
        if ((unsigned)hh >= (unsigned)H) continue;
        #pragma unroll
        for (int dk = -2; dk <= 2; dk++) {
            int ww = w + dk;
            if ((unsigned)ww < (unsigned)W) s += sb[hh * W + ww];
        }
    }
    g_xmax[p] = fmaxf(s, 5.0f);
}

// x_lateral + t = x_lateral / xmax / (1e-10 + rowsum), plus per-(b,o) max
__global__ void k_main(const float* __restrict__ x, float* __restrict__ out) {
    int pix = blockIdx.x * blockDim.x + threadIdx.x;   // blocks never straddle (b,o)
    int w_ = pix & 127;
    int h  = (pix >> 7) & 127;
    int bo = pix >> 14;
    int o  = bo & 63;
    int b  = bo >> 6;

    int n = g_nnz[o];
    const int*   ib = g_idx + o * TAPS;
    const float* vb = g_val + o * TAPS;
    const float* xb = x + (size_t)b * C * HW;

    float acc = 0.0f;
    for (int e = 0; e < n; e++) {
        int enc  = ib[e];
        float v  = vb[e];
        int ci = enc >> 8;
        int hh = h  + ((enc >> 4) & 15) - 2;
        int ww = w_ + (enc & 15) - 2;
        if ((unsigned)hh < (unsigned)H && (unsigned)ww < (unsigned)W)
            acc += v * xb[ci * HW + hh * W + ww];
    }
    out[pix] = acc;                                   // x_lateral

    float xm = g_xmax[b * HW + h * W + w_];
    float t  = acc / xm;
    t = t / (1e-10f + g_rowsum[o]);
    out[NOUT + pix] = t;                              // staged, finalized in k_final

    // block max -> atomic per (b,o)
    __shared__ float smax[8];
    float tm = t;
    #pragma unroll
    for (int off = 16; off; off >>= 1)
        tm = fmaxf(tm, __shfl_down_sync(0xffffffffu, tm, off));
    int lane = threadIdx.x & 31, wid = threadIdx.x >> 5;
    if (lane == 0) smax[wid] = tm;
    __syncthreads();
    if (wid == 0) {
        tm = (lane < 8) ? smax[lane] : -FLT_MAX;
        #pragma unroll
        for (int off = 4; off; off >>= 1)
            tm = fmaxf(tm, __shfl_down_sync(0xffffffffu, tm, off));
        if (lane == 0) atomicMaxF(&g_m[bo], tm);
    }
}

// xn = t / (1e-10 + m);  bin = (xn^3 >= 0.5)
__global__ void k_final(float* __restrict__ out) {
    int pix = blockIdx.x * blockDim.x + threadIdx.x;
    int bo  = pix >> 14;
    float t  = out[NOUT + pix];
    float xn = t / (1e-10f + g_m[bo]);
    out[NOUT + pix]     = xn;
    out[2 * NOUT + pix] = (xn * xn * xn >= 0.5f) ? 1.0f : 0.0f;
}

extern "C" void kernel_launch(void* const* d_in, const int* in_sizes, int n_in,
                              void* d_out, int out_size) {
    const float* x  = (const float*)d_in[0];
    const float* wm = (const float*)d_in[1];
    float* out = (float*)d_out;

    k_init_m<<<1, 256>>>();
    k_build<<<8, 256>>>(wm);
    k_chansum<<<NPIX / 256, 256>>>(x);
    k_box<<<NPIX / 256, 256>>>();
    k_main<<<NOUT / 256, 256>>>(x, out);
    k_final<<<NOUT / 256, 256>>>(out);
}

// round 5
// speedup vs baseline: 1.9934x; 1.9934x over previous
#include <cuda_runtime.h>
#include <float.h>

#define C    64
#define K5   5
#define KKT  25
#define TAPS (C*KKT)      // 1600
#define BB   4
#define H    128
#define W    128
#define HW   (H*W)        // 16384
#define NPIX (BB*HW)      // 65536
#define NOUT (BB*C*HW)    // 4194304
#define PPT  32           // pixels per thread in k_fused (512 thr * 32 = 16384)

// Scratch (static __device__ — no allocations allowed)
__device__ int   g_idx[C*TAPS];
__device__ float g_val[C*TAPS];
__device__ int   g_nnz[C];
__device__ float g_rowsum[C];
__device__ float g_s[NPIX];
__device__ float g_rxmax[NPIX];   // 1 / max(boxsum, 5)

// ---------------------------------------------------------------------------
// k_pre: blocks [0,256): channel-sum s[b,h,w]; blocks [256,264): CSR build of W
// ---------------------------------------------------------------------------
__global__ void k_pre(const float* __restrict__ x, const float* __restrict__ wmat) {
    if (blockIdx.x < NPIX / 256) {
        int p  = blockIdx.x * 256 + threadIdx.x;
        int b  = p >> 14;
        int hw = p & (HW - 1);
        const float* xb = x + (size_t)b * C * HW + hw;
        float s = 0.0f;
        #pragma unroll 16
        for (int i = 0; i < C; i++) s += __ldg(xb + i * HW);
        g_s[p] = s;
    } else {
        // one warp per output-channel row of W (64 x 1600)
        int warp = ((blockIdx.x - NPIX / 256) * 256 + threadIdx.x) >> 5;
        int lane = threadIdx.x & 31;
        if (warp >= C) return;
        const float* row = wmat + warp * TAPS;
        int cnt = 0;
        float rsum = 0.0f;
        for (int base = 0; base < TAPS; base += 32) {
            float v = row[base + lane];
            rsum += v;
            unsigned mask = __ballot_sync(0xffffffffu, v != 0.0f);
            if (v != 0.0f) {
                int pos = __popc(mask & ((1u << lane) - 1u));
                int k = base + lane;
                int ci  = k / KKT;
                int rem = k - ci * KKT;
                int dj  = rem / K5;
                int dk  = rem - dj * K5;
                g_idx[warp * TAPS + cnt + pos] = (ci << 8) | (dj << 4) | dk;
                g_val[warp * TAPS + cnt + pos] = v;
            }
            cnt += __popc(mask);
        }
        #pragma unroll
        for (int off = 16; off; off >>= 1)
            rsum += __shfl_down_sync(0xffffffffu, rsum, off);
        if (lane == 0) { g_nnz[warp] = cnt; g_rowsum[warp] = rsum; }
    }
}

// ---------------------------------------------------------------------------
// k_box: smem-tiled 5x5 box-sum of s; writes RECIPROCAL of max(sum, 5)
// grid: (32 bands, 4 batches); band = 4 output rows; 256 threads
// ---------------------------------------------------------------------------
__global__ void k_box() {
    __shared__ float ss[8][W];       // rows r0-2 .. r0+5
    int b    = blockIdx.y;
    int r0   = blockIdx.x * 4;
    int tid  = threadIdx.x;
    const float* sb = g_s + b * HW;

    #pragma unroll
    for (int k = 0; k < 4; k++) {            // 8*128 = 1024 loads / 256 thr
        int j  = tid + k * 256;
        int rr = r0 - 2 + (j >> 7);
        int cc = j & 127;
        ss[j >> 7][cc] = ((unsigned)rr < (unsigned)H) ? sb[rr * W + cc] : 0.0f;
    }
    __syncthreads();

    #pragma unroll
    for (int k = 0; k < 2; k++) {            // 4*128 = 512 outputs / 256 thr
        int j  = tid + k * 256;
        int jr = j >> 7;                     // 0..3
        int w_ = j & 127;
        float s = 0.0f;
        #pragma unroll
        for (int dj = 0; dj < 5; dj++) {
            #pragma unroll
            for (int dk = 0; dk < 5; dk++) {
                int ww = w_ + dk - 2;
                if ((unsigned)ww < (unsigned)W) s += ss[jr + dj][ww];
            }
        }
        g_rxmax[b * HW + (r0 + jr) * W + w_] = 1.0f / fmaxf(s, 5.0f);
    }
}

// ---------------------------------------------------------------------------
// k_fused: one block per (b,o) plane. Computes x_lateral, block-local spatial
// max, xn, and bin — all three outputs in one pass. 512 threads, 32 pix/thread.
// ---------------------------------------------------------------------------
__global__ void __launch_bounds__(512) k_fused(const float* __restrict__ x,
                                               float* __restrict__ out) {
    int bo  = blockIdx.x;
    int o   = bo & 63;
    int b   = bo >> 6;
    int tid = threadIdx.x;

    float acc[PPT];
    #pragma unroll
    for (int i = 0; i < PPT; i++) acc[i] = 0.0f;

    int n = g_nnz[o];
    const float* xb = x + (size_t)b * C * HW;

    for (int e = 0; e < n; e++) {
        int   enc = g_idx[o * TAPS + e];     // block-uniform
        float v   = g_val[o * TAPS + e];
        int ci = enc >> 8;
        int dj = ((enc >> 4) & 15) - 2;
        int dk = (enc & 15) - 2;
        const float* xp = xb + ci * HW;
        #pragma unroll
        for (int i = 0; i < PPT; i++) {
            int pix = tid + i * 512;
            int h = pix >> 7, w_ = pix & 127;
            int hh = h + dj, ww = w_ + dk;
            if ((unsigned)hh < (unsigned)H && (unsigned)ww < (unsigned)W)
                acc[i] += v * __ldg(xp + hh * W + ww);
        }
    }

    float inv_rs = 1.0f / (1e-10f + g_rowsum[o]);
    const float* rxm = g_rxmax + b * HW;     // L2-resident (256 KB total)
    float* o0 = out + (size_t)bo * HW;

    float m = -FLT_MAX;
    #pragma unroll
    for (int i = 0; i < PPT; i++) {
        int pix = tid + i * 512;
        o0[pix] = acc[i];                                // x_lateral
        float t = acc[i] * rxm[pix] * inv_rs;
        acc[i] = t;                                      // reuse regs for t
        m = fmaxf(m, t);
    }

    // block-wide max over 512 threads
    __shared__ float smax[16];
    __shared__ float bmax;
    #pragma unroll
    for (int off = 16; off; off >>= 1)
        m = fmaxf(m, __shfl_down_sync(0xffffffffu, m, off));
    int lane = tid & 31, wid = tid >> 5;
    if (lane == 0) smax[wid] = m;
    __syncthreads();
    if (tid == 0) {
        float mm = smax[0];
        #pragma unroll
        for (int j = 1; j < 16; j++) mm = fmaxf(mm, smax[j]);
        bmax = mm;
    }
    __syncthreads();

    float inv_m = 1.0f / (1e-10f + bmax);
    float* o1 = out + NOUT + (size_t)bo * HW;
    float* o2 = out + 2 * NOUT + (size_t)bo * HW;
    #pragma unroll
    for (int i = 0; i < PPT; i++) {
        int pix = tid + i * 512;
        float xn = acc[i] * inv_m;
        o1[pix] = xn;
        o2[pix] = (xn * xn * xn >= 0.5f) ? 1.0f : 0.0f;
    }
}

extern "C" void kernel_launch(void* const* d_in, const int* in_sizes, int n_in,
                              void* d_out, int out_size) {
    const float* x  = (const float*)d_in[0];
    const float* wm = (const float*)d_in[1];
    float* out = (float*)d_out;

    k_pre<<<NPIX / 256 + 8, 256>>>(x, wm);     // chansum + CSR build
    k_box<<<dim3(32, 4), 256>>>();             // smem-tiled box + reciprocal
    k_fused<<<BB * C, 512>>>(x, out);          // conv + norms + max + bin
}

// round 6
// speedup vs baseline: 2.3163x; 1.1620x over previous
#include <cuda_runtime.h>
#include <float.h>

#define C    64
#define K5   5
#define KKT  25
#define TAPS (C*KKT)      // 1600
#define BB   4
#define H    128
#define W    128
#define HW   (H*W)        // 16384
#define NPIX (BB*HW)      // 65536
#define NOUT (BB*C*HW)    // 4194304
#define PPT  32           // pixels per thread in k_fused

// Scratch (static __device__ — no allocations allowed)
__device__ int   g_idx[C*TAPS];
__device__ float g_val[C*TAPS];
__device__ int   g_nnz[C];
__device__ float g_rowsum[C];
__device__ float g_part[8*NPIX];  // 8-way channel-split partial sums (2 MB)
__device__ float g_rxmax[NPIX];   // 1 / max(boxsum, 5)

// ---------------------------------------------------------------------------
// k_pre: blocks [0,512): channel-sum partials (float4, 8 channels/block)
//        blocks [512,576): CSR build, ONE BLOCK per W row (loads up-front)
// ---------------------------------------------------------------------------
__global__ void k_pre(const float* __restrict__ x, const float* __restrict__ wmat) {
    int blk = blockIdx.x;
    int t   = threadIdx.x;

    if (blk < 512) {
        // tile 0..15 (256 float4 each), cg 0..7 (8 channels), b 0..3
        int tile = blk & 15, cg = (blk >> 4) & 7, b = blk >> 7;
        int p4 = tile * 256 + t;                       // float4 index in plane
        const float4* xb = (const float4*)(x + (size_t)b * C * HW) + p4;
        float4 s = make_float4(0.f, 0.f, 0.f, 0.f);
        #pragma unroll
        for (int i = 0; i < 8; i++) {
            float4 v = __ldg(xb + (cg * 8 + i) * (HW / 4));
            s.x += v.x; s.y += v.y; s.z += v.z; s.w += v.w;
        }
        ((float4*)g_part)[cg * (NPIX / 4) + b * (HW / 4) + p4] = s;
    } else {
        int row = blk - 512;                           // 0..63
        // load entire 1600-wide row up-front: 7 independent loads/thread
        float v[7];
        #pragma unroll
        for (int k = 0; k < 7; k++) {
            int idx = k * 256 + t;
            v[k] = (idx < TAPS) ? __ldg(wmat + row * TAPS + idx) : 0.0f;
        }
        // row sum
        float rs = ((v[0]+v[1]) + (v[2]+v[3])) + ((v[4]+v[5]) + v[6]);
        __shared__ float ssum[8];
        __shared__ int   wc[8];
        int lane = t & 31, wid = t >> 5;
        #pragma unroll
        for (int off = 16; off; off >>= 1)
            rs += __shfl_down_sync(0xffffffffu, rs, off);
        if (lane == 0) ssum[wid] = rs;
        __syncthreads();
        if (t == 0) {
            float a = 0.f;
            #pragma unroll
            for (int j = 0; j < 8; j++) a += ssum[j];
            g_rowsum[row] = a;
        }
        // stable compaction: per 256-chunk ballot + warp-count scan (all ALU)
        int base = 0;
        #pragma unroll
        for (int k = 0; k < 7; k++) {
            unsigned mask = __ballot_sync(0xffffffffu, v[k] != 0.0f);
            if (lane == 0) wc[wid] = __popc(mask);
            __syncthreads();
            int pre = 0, tot = 0;
            #pragma unroll
            for (int j = 0; j < 8; j++) { int c = wc[j]; if (j < wid) pre += c; tot += c; }
            if (v[k] != 0.0f) {
                int pos = base + pre + __popc(mask & ((1u << lane) - 1u));
                int idx = k * 256 + t;
                int ci  = idx / KKT;
                int rem = idx - ci * KKT;
                int dj  = rem / K5;
                int dk  = rem - dj * K5;
                g_idx[row * TAPS + pos] = (ci << 8) | (dj << 4) | dk;
                g_val[row * TAPS + pos] = v[k];
            }
            base += tot;
            __syncthreads();
        }
        if (t == 0) g_nnz[row] = base;
    }
}

// ---------------------------------------------------------------------------
// k_box: sums the 8 partials into a smem tile, 5x5 box, writes 1/max(s,5).
// grid: (64 bands of 2 rows, 4 batches); 256 threads
// ---------------------------------------------------------------------------
__global__ void k_box() {
    __shared__ float ss[6][W];                 // rows r0-2 .. r0+3
    int b  = blockIdx.y;
    int r0 = blockIdx.x * 2;
    int t  = threadIdx.x;

    #pragma unroll
    for (int k = 0; k < 3; k++) {              // 6*128 = 768 tile entries
        int j  = t + k * 256;
        int rr = r0 - 2 + (j >> 7);
        int cc = j & 127;
        float s = 0.0f;
        if ((unsigned)rr < (unsigned)H) {
            int off = b * HW + rr * W + cc;
            #pragma unroll
            for (int g = 0; g < 8; g++) s += g_part[g * NPIX + off];   // L2-resident
        }
        ss[j >> 7][cc] = s;
    }
    __syncthreads();

    int jr = t >> 7;                           // 0..1
    int w_ = t & 127;
    float s = 0.0f;
    #pragma unroll
    for (int dj = 0; dj < 5; dj++) {
        #pragma unroll
        for (int dk = 0; dk < 5; dk++) {
            int ww = w_ + dk - 2;
            if ((unsigned)ww < (unsigned)W) s += ss[jr + dj][ww];
        }
    }
    g_rxmax[b * HW + (r0 + jr) * W + w_] = 1.0f / fmaxf(s, 5.0f);
}

// ---------------------------------------------------------------------------
// k_fused: one block per (b,o) plane. x_lateral + block-local spatial max +
// xn + bin in one pass. 512 threads, 32 pix/thread.
// ---------------------------------------------------------------------------
__global__ void __launch_bounds__(512) k_fused(const float* __restrict__ x,
                                               float* __restrict__ out) {
    int bo  = blockIdx.x;
    int o   = bo & 63;
    int b   = bo >> 6;
    int tid = threadIdx.x;

    float acc[PPT];
    #pragma unroll
    for (int i = 0; i < PPT; i++) acc[i] = 0.0f;

    int n = g_nnz[o];
    const float* xb = x + (size_t)b * C * HW;

    for (int e = 0; e < n; e++) {
        int   enc = g_idx[o * TAPS + e];       // block-uniform
        float v   = g_val[o * TAPS + e];
        int ci = enc >> 8;
        int dj = ((enc >> 4) & 15) - 2;
        int dk = (enc & 15) - 2;
        const float* xp = xb + ci * HW;
        #pragma unroll
        for (int i = 0; i < PPT; i++) {
            int pix = tid + i * 512;
            int h = pix >> 7, w_ = pix & 127;
            int hh = h + dj, ww = w_ + dk;
            if ((unsigned)hh < (unsigned)H && (unsigned)ww < (unsigned)W)
                acc[i] += v * __ldg(xp + hh * W + ww);
        }
    }

    float inv_rs = 1.0f / (1e-10f + g_rowsum[o]);
    const float* rxm = g_rxmax + b * HW;       // L2-resident (256 KB total)
    float* o0 = out + (size_t)bo * HW;

    float m = -FLT_MAX;
    #pragma unroll
    for (int i = 0; i < PPT; i++) {
        int pix = tid + i * 512;
        o0[pix] = acc[i];                      // x_lateral
        float t = acc[i] * rxm[pix] * inv_rs;
        acc[i] = t;
        m = fmaxf(m, t);
    }

    __shared__ float smax[16];
    __shared__ float bmax;
    #pragma unroll
    for (int off = 16; off; off >>= 1)
        m = fmaxf(m, __shfl_down_sync(0xffffffffu, m, off));
    int lane = tid & 31, wid = tid >> 5;
    if (lane == 0) smax[wid] = m;
    __syncthreads();
    if (tid == 0) {
        float mm = smax[0];
        #pragma unroll
        for (int j = 1; j < 16; j++) mm = fmaxf(mm, smax[j]);
        bmax = mm;
    }
    __syncthreads();

    float inv_m = 1.0f / (1e-10f + bmax);
    float* o1 = out + NOUT + (size_t)bo * HW;
    float* o2 = out + 2 * NOUT + (size_t)bo * HW;
    #pragma unroll
    for (int i = 0; i < PPT; i++) {
        int pix = tid + i * 512;
        float xn = acc[i] * inv_m;
        o1[pix] = xn;
        o2[pix] = (xn * xn * xn >= 0.5f) ? 1.0f : 0.0f;
    }
}

extern "C" void kernel_launch(void* const* d_in, const int* in_sizes, int n_in,
                              void* d_out, int out_size) {
    const float* x  = (const float*)d_in[0];
    const float* wm = (const float*)d_in[1];
    float* out = (float*)d_out;

    k_pre<<<576, 256>>>(x, wm);            // chansum partials + fast CSR build
    k_box<<<dim3(64, 4), 256>>>();         // partial-sum + box + reciprocal
    k_fused<<<BB * C, 512>>>(x, out);      // conv + norms + max + bin
}